// round 8
// baseline (speedup 1.0000x reference)
#include <cuda_runtime.h>
#include <cuda_fp16.h>
#include <cstdint>

// ---------------------------------------------------------------------------
// MovePredictor: logits = W3 . relu(W2 . relu(W1.[e_src;e_tgt] + b1) + b2) + b3
//  - PQ = emb @ [W1_left; W1_right]^T over NODES (b1 folded into P), fp16
//  - h1[m] = relu(PQ[src,:512] + PQ[tgt,512:]) built on the fly in smem
//  - fp16 2-pass GEMMs (data fp16, weights hi+lo fp16), mma.sync m16n8k16
//  - 256-thread CTAs (2 CTAs/SM), tile 128x128, warp tile 64x32,
//    BK=64, 2-stage cp.async pipeline.
// ---------------------------------------------------------------------------

#define N_NODES_MAX 100000
#define EMB_D   256
#define H1DIM   512
#define H2DIM   256
#define PQN     1024

#define BM 128
#define BN 128
#define BK 64                    // fp16 per k-chunk: 128B rows
#define RS 144                   // 128B data + 16B pad (16B-aligned)
#define NT 256

#define A_O  0                   // 128 x 144 = 18432
#define BH_O 18432               // 128 x 144
#define BL_O 36864               // 128 x 144
#define STG  55296
#define NSTG 2
#define AUXO (STG * NSTG)        // 110592
#define SMEM_TOTAL (AUXO + 2048)

// ---- device globals (allocation-free scratch) ----
__device__ __half g_PQh[(size_t)N_NODES_MAX * PQN];    // 204.8 MB
__device__ __half g_Eh[(size_t)N_NODES_MAX * EMB_D];
__device__ __half g_W1sh[(size_t)PQN * EMB_D];
__device__ __half g_W1sl[(size_t)PQN * EMB_D];
__device__ __half g_W2h[(size_t)H2DIM * H1DIM];
__device__ __half g_W2l[(size_t)H2DIM * H1DIM];

// ---------------- helpers ----------------
__device__ __forceinline__ uint32_t smem_u32(const void* p) {
    uint32_t a;
    asm("{ .reg .u64 t; cvta.to.shared.u64 t, %1; cvt.u32.u64 %0, t; }"
        : "=r"(a) : "l"(p));
    return a;
}
__device__ __forceinline__ void cp16(uint32_t dst, const void* src) {
    asm volatile("cp.async.cg.shared.global [%0], [%1], 16;" :: "r"(dst), "l"(src));
}
__device__ __forceinline__ void cp_commit() {
    asm volatile("cp.async.commit_group;" ::: "memory");
}
__device__ __forceinline__ void cp_wait0() {
    asm volatile("cp.async.wait_group 0;" ::: "memory");
}
__device__ __forceinline__ void cp_wait1() {
    asm volatile("cp.async.wait_group 1;" ::: "memory");
}
__device__ __forceinline__ void ldsm_x4(uint32_t* r, uint32_t addr) {
    asm volatile("ldmatrix.sync.aligned.m8n8.x4.shared.b16 {%0,%1,%2,%3}, [%4];"
                 : "=r"(r[0]), "=r"(r[1]), "=r"(r[2]), "=r"(r[3]) : "r"(addr));
}
__device__ __forceinline__ void mma_f16(float* c, const uint32_t* a,
                                        uint32_t b0, uint32_t b1) {
    asm volatile(
        "mma.sync.aligned.m16n8k16.row.col.f32.f16.f16.f32 "
        "{%0,%1,%2,%3}, {%4,%5,%6,%7}, {%8,%9}, {%0,%1,%2,%3};"
        : "+f"(c[0]), "+f"(c[1]), "+f"(c[2]), "+f"(c[3])
        : "r"(a[0]), "r"(a[1]), "r"(a[2]), "r"(a[3]), "r"(b0), "r"(b1));
}

// 64x32 warp tile over one 64-k chunk (4 k16 steps), pass-major hi then lo.
__device__ __forceinline__ void mma_chunk(uint32_t stg, int lane, int warp_m,
                                          int warp_n, float acc[4][4][4]) {
    const uint32_t aB = stg + A_O  + (warp_m * 64 + (lane & 15)) * RS + (lane >> 4) * 16;
    const uint32_t bB = stg + BH_O + (warp_n * 32 + (lane & 15)) * RS + (lane >> 4) * 16;
    #pragma unroll
    for (int kt = 0; kt < 4; kt++) {
        uint32_t aR[4][4], bH[2][4], bL[2][4];
        #pragma unroll
        for (int mt = 0; mt < 4; mt++)
            ldsm_x4(aR[mt], aB + mt * 16 * RS + kt * 32);
        #pragma unroll
        for (int nb = 0; nb < 2; nb++) {
            ldsm_x4(bH[nb], bB + nb * 16 * RS + kt * 32);
            ldsm_x4(bL[nb], bB + (BL_O - BH_O) + nb * 16 * RS + kt * 32);
        }
        #pragma unroll
        for (int mt = 0; mt < 4; mt++)
            #pragma unroll
            for (int nb = 0; nb < 2; nb++) {
                mma_f16(acc[mt][2 * nb],     aR[mt], bH[nb][0], bH[nb][2]);
                mma_f16(acc[mt][2 * nb + 1], aR[mt], bH[nb][1], bH[nb][3]);
            }
        #pragma unroll
        for (int mt = 0; mt < 4; mt++)
            #pragma unroll
            for (int nb = 0; nb < 2; nb++) {
                mma_f16(acc[mt][2 * nb],     aR[mt], bL[nb][0], bL[nb][2]);
                mma_f16(acc[mt][2 * nb + 1], aR[mt], bL[nb][1], bL[nb][3]);
            }
    }
}

// ---------------- prep ----------------
__global__ void prep_split(const float* __restrict__ emb, int n_emb,
                           const float* __restrict__ W1,
                           const float* __restrict__ W2)
{
    int total = n_emb + PQN * EMB_D + H2DIM * H1DIM;
    for (int i = blockIdx.x * blockDim.x + threadIdx.x; i < total;
         i += gridDim.x * blockDim.x) {
        if (i < n_emb) {
            g_Eh[i] = __float2half_rn(emb[i]);
        } else if (i < n_emb + PQN * EMB_D) {
            int j = i - n_emb;
            int r = j >> 8, k = j & 255;
            float x = W1[(size_t)(r & 511) * 512 + k + ((r >> 9) << 8)];
            __half h = __float2half_rn(x);
            g_W1sh[j] = h;
            g_W1sl[j] = __float2half_rn(x - __half2float(h));
        } else {
            int j = i - n_emb - PQN * EMB_D;
            float x = W2[j];
            __half h = __float2half_rn(x);
            g_W2h[j] = h;
            g_W2l[j] = __float2half_rn(x - __half2float(h));
        }
    }
}
__global__ void init_out(float* __restrict__ out, const float* __restrict__ b3, int M)
{
    int i = blockIdx.x * blockDim.x + threadIdx.x;
    if (i < M) out[i] = b3[0];
}

// ---------------- GEMM 1: PQ = emb @ W1s^T (+b1 on P half), fp16 out ----------------
__global__ __launch_bounds__(NT, 2)
void gemm_pq(const float* __restrict__ b1, int n_nodes)
{
    extern __shared__ char sm[];
    const uint32_t sb = smem_u32(sm);
    const int t = threadIdx.x, lane = t & 31, w = t >> 5;
    const int warp_m = w >> 2, warp_n = w & 3;
    const int m0 = blockIdx.y * BM;
    const int n0 = blockIdx.x * BN;

    float acc[4][4][4];
    #pragma unroll
    for (int a = 0; a < 4; a++)
        #pragma unroll
        for (int b = 0; b < 4; b++)
            #pragma unroll
            for (int c = 0; c < 4; c++) acc[a][b][c] = 0.f;

    auto issue = [&](int stage, int ch) {
        uint32_t sg = sb + stage * STG;
        int k0 = ch * BK;
        #pragma unroll
        for (int i = 0; i < 4; i++) {            // A: 1024 cp16
            int g = t + i * NT;
            int row = g >> 3, c = g & 7;
            int gm = m0 + row; if (gm >= n_nodes) gm = n_nodes - 1;
            cp16(sg + A_O + row * RS + c * 16,
                 g_Eh + (size_t)gm * EMB_D + k0 + c * 8);
        }
        #pragma unroll
        for (int i = 0; i < 8; i++) {            // B hi+lo: 2048 cp16
            int g = t + i * NT;
            int buf = g >> 10, rem = g & 1023;
            int row = rem >> 3, c = rem & 7;
            const __half* src = (buf ? g_W1sl : g_W1sh) +
                                (size_t)(n0 + row) * EMB_D + k0 + c * 8;
            cp16(sg + (buf ? BL_O : BH_O) + row * RS + c * 16, src);
        }
        cp_commit();
    };

    const int CH = EMB_D / BK;       // 4
    issue(0, 0);
    for (int ch = 0; ch < CH; ch++) {
        const bool more = (ch + 1 < CH);
        if (more) issue((ch + 1) & 1, ch + 1);
        if (more) cp_wait1(); else cp_wait0();
        __syncthreads();
        mma_chunk(sb + (ch & 1) * STG, lane, warp_m, warp_n, acc);
        __syncthreads();
    }

    // store fp16 PQ; fold b1 into the P half (global cols < 512)
    #pragma unroll
    for (int mt = 0; mt < 4; mt++)
        #pragma unroll
        for (int h = 0; h < 2; h++) {
            int r = m0 + warp_m * 64 + mt * 16 + (lane >> 2) + 8 * h;
            if (r < n_nodes) {
                #pragma unroll
                for (int nb = 0; nb < 4; nb++) {
                    int c = n0 + warp_n * 32 + nb * 8 + (lane & 3) * 2;
                    float v0 = acc[mt][nb][2 * h];
                    float v1 = acc[mt][nb][2 * h + 1];
                    if (c < 512) { v0 += b1[c]; v1 += b1[c + 1]; }
                    *(__half2*)(g_PQh + (size_t)r * PQN + c) =
                        __floats2half2_rn(v0, v1);
                }
            }
        }
}

// ---------------- GEMM 2+3: h1 on-the-fly, GEMM vs W2 slice, relu, dot W3 ----------------
__global__ __launch_bounds__(NT, 2)
void gemm_l23(const int* __restrict__ edge_index,
              const int* __restrict__ move_idx, int n_edges,
              const float* __restrict__ b2,
              const float* __restrict__ W3, float* __restrict__ out, int M)
{
    extern __shared__ char sm[];
    const uint32_t sb = smem_u32(sm);
    const int t = threadIdx.x, lane = t & 31, w = t >> 5;
    const int warp_m = w >> 2, warp_n = w & 3;
    const int m0 = blockIdx.y * BM;
    const int n0 = blockIdx.x * BN;      // 0 or 128

    int*   offS = (int*)(sm + AUXO);
    int*   offT = (int*)(sm + AUXO + 512);
    float* b2s  = (float*)(sm + AUXO + 1024);   // 128 floats (slice-local)
    float* w3s  = (float*)(sm + AUXO + 1536);   // 128 floats

    if (t < 128) {
        int m = m0 + t; if (m >= M) m = M - 1;
        int e = move_idx[m];
        offS[t] = edge_index[e] * PQN;
        offT[t] = edge_index[n_edges + e] * PQN + 512;
    } else {
        int c = t - 128;
        b2s[c] = b2[n0 + c];
        w3s[c] = W3[n0 + c];
    }
    __syncthreads();

    float acc[4][4][4];
    #pragma unroll
    for (int a = 0; a < 4; a++)
        #pragma unroll
        for (int b = 0; b < 4; b++)
            #pragma unroll
            for (int c = 0; c < 4; c++) acc[a][b][c] = 0.f;

    const int r  = t >> 1;           // A row (0..127)
    const int hh = t & 1;            // 32-half half of the 64-half chunk

    auto issueB = [&](int stage, int ch) {
        uint32_t sg = sb + stage * STG;
        int k0 = ch * BK;
        #pragma unroll
        for (int i = 0; i < 8; i++) {
            int g = t + i * NT;
            int buf = g >> 10, rem = g & 1023;
            int row = rem >> 3, c = rem & 7;
            const __half* src = (buf ? g_W2l : g_W2h) +
                                (size_t)(n0 + row) * H1DIM + k0 + c * 8;
            cp16(sg + (buf ? BL_O : BH_O) + row * RS + c * 16, src);
        }
        cp_commit();
    };
    // gather + add + relu -> fp16 A rows in smem (stage)
    auto buildA = [&](int stage, int ch) {
        const __half* ps = g_PQh + offS[r] + ch * BK + hh * 32;
        const __half* pt = g_PQh + offT[r] + ch * BK + hh * 32;
        uint4 S[4], T[4];
        #pragma unroll
        for (int q = 0; q < 4; q++) {
            S[q] = *(const uint4*)(ps + q * 8);
            T[q] = *(const uint4*)(pt + q * 8);
        }
        uint32_t o = stage * STG + A_O + r * RS + hh * 64;
        const __half2 z = __floats2half2_rn(0.f, 0.f);
        #pragma unroll
        for (int q = 0; q < 4; q++) {
            uint4 v;
            const __half2* s2 = (const __half2*)&S[q];
            const __half2* t2 = (const __half2*)&T[q];
            __half2* v2 = (__half2*)&v;
            #pragma unroll
            for (int j = 0; j < 4; j++)
                v2[j] = __hmax2(__hadd2(s2[j], t2[j]), z);
            *(uint4*)(sm + o + q * 16) = v;
        }
    };

    const int CH = H1DIM / BK;       // 8
    issueB(0, 0);
    buildA(0, 0);
    for (int ch = 0; ch < CH; ch++) {
        const bool more = (ch + 1 < CH);
        if (more) issueB((ch + 1) & 1, ch + 1);
        if (more) cp_wait1(); else cp_wait0();
        __syncthreads();
        if (more) buildA((ch + 1) & 1, ch + 1);   // writes other stage: safe
        mma_chunk(sb + (ch & 1) * STG, lane, warp_m, warp_n, acc);
        __syncthreads();
    }

    // epilogue: +b2, relu, dot w3, quad-reduce, atomicAdd partials
    #pragma unroll
    for (int mt = 0; mt < 4; mt++)
        #pragma unroll
        for (int h = 0; h < 2; h++) {
            int rr = m0 + warp_m * 64 + mt * 16 + (lane >> 2) + 8 * h;
            float p = 0.f;
            #pragma unroll
            for (int nb = 0; nb < 4; nb++) {
                int c = warp_n * 32 + nb * 8 + (lane & 3) * 2;
                float v0 = acc[mt][nb][2 * h]     + b2s[c];
                float v1 = acc[mt][nb][2 * h + 1] + b2s[c + 1];
                v0 = v0 > 0.f ? v0 : 0.f;
                v1 = v1 > 0.f ? v1 : 0.f;
                p += v0 * w3s[c] + v1 * w3s[c + 1];
            }
            p += __shfl_xor_sync(0xffffffffu, p, 1);
            p += __shfl_xor_sync(0xffffffffu, p, 2);
            if ((lane & 3) == 0 && rr < M) atomicAdd(out + rr, p);
        }
}

// ---------------- launch ----------------
extern "C" void kernel_launch(void* const* d_in, const int* in_sizes, int n_in,
                              void* d_out, int out_size)
{
    const float* emb        = (const float*)d_in[0];
    const int*   edge_index = (const int*)d_in[1];
    const int*   move_idx   = (const int*)d_in[2];
    const float* W1 = (const float*)d_in[3];
    const float* b1 = (const float*)d_in[4];
    const float* W2 = (const float*)d_in[5];
    const float* b2 = (const float*)d_in[6];
    const float* W3 = (const float*)d_in[7];
    const float* b3 = (const float*)d_in[8];
    float* out = (float*)d_out;

    int n_emb   = in_sizes[0];
    int n_nodes = n_emb / EMB_D;
    int n_edges = in_sizes[1] / 2;
    int M       = in_sizes[2];
    int mtiles  = (M + BM - 1) / BM;
    int ntiles  = (n_nodes + BM - 1) / BM;

    cudaFuncSetAttribute(gemm_pq,  cudaFuncAttributeMaxDynamicSharedMemorySize, SMEM_TOTAL);
    cudaFuncSetAttribute(gemm_l23, cudaFuncAttributeMaxDynamicSharedMemorySize, SMEM_TOTAL);

    prep_split<<<512, 256>>>(emb, n_emb, W1, W2);
    init_out<<<(M + 255) / 256, 256>>>(out, b3, M);
    {
        dim3 grid(PQN / BN, ntiles);         // 8 x 782
        gemm_pq<<<grid, NT, SMEM_TOTAL>>>(b1, n_nodes);
    }
    {
        dim3 grid(H2DIM / BN, mtiles);       // 2 x 1563
        gemm_l23<<<grid, NT, SMEM_TOTAL>>>(edge_index, move_idx, n_edges,
                                           b2, W3, out, M);
    }
}